// round 1
// baseline (speedup 1.0000x reference)
#include <cuda_runtime.h>
#include <cstdint>
#include <cstddef>

// Problem constants: B=4, C=128, N=64, HID=1536, PROJ=768
// feat: [B*3N, C] = [768, 128]
// h:    [768, 1536]
// out:  [768, 768]

__device__ float g_feat[768 * 128];
__device__ float g_hbuf[768 * 1536];

// ---------------------------------------------------------------------------
// Kernel 1: streaming reduction. One CTA per (b,c) slab of 64^3 floats (1 MB).
// Computes sum over (h,w) per d; sum over (d,w) per h; sum over (d,h) per w
// of x^2, divides by 4096, writes feat[b*192 + {d | 64+h | 128+w}][c].
// Thread mapping: j = tid&15 -> float4 column within a 64-float row,
// g = tid>>4 -> row group; thread handles rows r = g + 16k, k=0..255.
// Within 4 consecutive k, d = r>>6 is constant (= k4), h cycles over
// {g, g+16, g+32, g+48}.
// ---------------------------------------------------------------------------
__global__ void __launch_bounds__(256) reduce_kernel(const float* __restrict__ x) {
    __shared__ float sc_s[64];   // per-d
    __shared__ float ss_s[64];   // per-h
    __shared__ float sa_s[64];   // per-w
    const int tid = threadIdx.x;
    if (tid < 64) { sc_s[tid] = 0.f; ss_s[tid] = 0.f; sa_s[tid] = 0.f; }
    __syncthreads();

    const int bc = blockIdx.x;                 // b*128 + c
    const float4* base = reinterpret_cast<const float4*>(x) + (size_t)bc * 65536;
    const int j = tid & 15;
    const int g = tid >> 4;
    const float4* p = base + (g << 4) + j;     // row r float4 index = r*16 + j

    float w0 = 0.f, w1 = 0.f, w2 = 0.f, w3 = 0.f;
    float ha0 = 0.f, ha1 = 0.f, ha2 = 0.f, ha3 = 0.f;

    for (int k4 = 0; k4 < 64; ++k4) {
        const float4* q = p + (size_t)k4 * 1024;   // 4 rows * 256 float4 stride
        float dacc;
        {
            float4 v = q[0];
            float s0 = v.x * v.x, s1 = v.y * v.y, s2 = v.z * v.z, s3 = v.w * v.w;
            w0 += s0; w1 += s1; w2 += s2; w3 += s3;
            float s = (s0 + s1) + (s2 + s3);
            ha0 += s; dacc = s;
        }
        {
            float4 v = q[256];
            float s0 = v.x * v.x, s1 = v.y * v.y, s2 = v.z * v.z, s3 = v.w * v.w;
            w0 += s0; w1 += s1; w2 += s2; w3 += s3;
            float s = (s0 + s1) + (s2 + s3);
            ha1 += s; dacc += s;
        }
        {
            float4 v = q[512];
            float s0 = v.x * v.x, s1 = v.y * v.y, s2 = v.z * v.z, s3 = v.w * v.w;
            w0 += s0; w1 += s1; w2 += s2; w3 += s3;
            float s = (s0 + s1) + (s2 + s3);
            ha2 += s; dacc += s;
        }
        {
            float4 v = q[768];
            float s0 = v.x * v.x, s1 = v.y * v.y, s2 = v.z * v.z, s3 = v.w * v.w;
            w0 += s0; w1 += s1; w2 += s2; w3 += s3;
            float s = (s0 + s1) + (s2 + s3);
            ha3 += s; dacc += s;
        }
        // reduce dacc over the 16 threads (j) of this group: all share d = k4
        dacc += __shfl_xor_sync(0xffffffffu, dacc, 8);
        dacc += __shfl_xor_sync(0xffffffffu, dacc, 4);
        dacc += __shfl_xor_sync(0xffffffffu, dacc, 2);
        dacc += __shfl_xor_sync(0xffffffffu, dacc, 1);
        if (j == 0) atomicAdd(&sc_s[k4], dacc);   // 16 groups hit same addr, cheap
    }

    // per-h sums: reduce each hacc over the 16 threads of the group, then the
    // group's h slot is unique -> plain store.
    {
        float v = ha0;
        v += __shfl_xor_sync(0xffffffffu, v, 8);
        v += __shfl_xor_sync(0xffffffffu, v, 4);
        v += __shfl_xor_sync(0xffffffffu, v, 2);
        v += __shfl_xor_sync(0xffffffffu, v, 1);
        if (j == 0) ss_s[g] = v;
    }
    {
        float v = ha1;
        v += __shfl_xor_sync(0xffffffffu, v, 8);
        v += __shfl_xor_sync(0xffffffffu, v, 4);
        v += __shfl_xor_sync(0xffffffffu, v, 2);
        v += __shfl_xor_sync(0xffffffffu, v, 1);
        if (j == 0) ss_s[g + 16] = v;
    }
    {
        float v = ha2;
        v += __shfl_xor_sync(0xffffffffu, v, 8);
        v += __shfl_xor_sync(0xffffffffu, v, 4);
        v += __shfl_xor_sync(0xffffffffu, v, 2);
        v += __shfl_xor_sync(0xffffffffu, v, 1);
        if (j == 0) ss_s[g + 32] = v;
    }
    {
        float v = ha3;
        v += __shfl_xor_sync(0xffffffffu, v, 8);
        v += __shfl_xor_sync(0xffffffffu, v, 4);
        v += __shfl_xor_sync(0xffffffffu, v, 2);
        v += __shfl_xor_sync(0xffffffffu, v, 1);
        if (j == 0) ss_s[g + 48] = v;
    }

    // per-w sums: w = 4j + lane component; reduce across the 16 groups via
    // shared atomics (<= 2-way same-address conflict inside a warp).
    atomicAdd(&sa_s[4 * j + 0], w0);
    atomicAdd(&sa_s[4 * j + 1], w1);
    atomicAdd(&sa_s[4 * j + 2], w2);
    atomicAdd(&sa_s[4 * j + 3], w3);

    __syncthreads();

    const int b = bc >> 7;
    const int c = bc & 127;
    if (tid < 192) {
        float v = (tid < 64) ? sc_s[tid]
                : (tid < 128) ? ss_s[tid - 64]
                : sa_s[tid - 128];
        g_feat[(size_t)(b * 192 + tid) * 128 + c] = v * (1.0f / 4096.0f);
    }
}

// ---------------------------------------------------------------------------
// FFMA2-based SGEMM: C[M,N] = A[M,K] @ Bw[K,N] + bias (optional ReLU).
// BM=BN=64, BK=16, 256 threads, 4x4 per-thread microtile.
// A staged k-major As[k][m]; B staged duplicated (each n value stored twice as
// float2) so packed f32x2 FMAs need no pack movs:
//   acc[p][q] (f32x2 over m-pair) += (a_m, a_m+1) * (b_n, b_n) elementwise.
// All of M, N, K are multiples of the tile sizes for both calls -> no guards.
// ---------------------------------------------------------------------------
__device__ __forceinline__ void fma2(unsigned long long& d,
                                     unsigned long long a,
                                     unsigned long long b) {
    asm("fma.rn.f32x2 %0, %1, %2, %0;" : "+l"(d) : "l"(a), "l"(b));
}

template <bool RELU>
__global__ void __launch_bounds__(256) gemm_kernel(const float* __restrict__ A,
                                                   const float* __restrict__ Bw,
                                                   const float* __restrict__ bias,
                                                   float* __restrict__ C,
                                                   int M, int N, int K) {
    __shared__ float  As[16][64];    // [k][m]
    __shared__ float2 Bs[16][64];    // [k][n], duplicated

    const int tid = threadIdx.x;
    const int tx = tid & 15;         // n-tile coordinate
    const int ty = tid >> 4;         // m-tile coordinate
    const int m0 = blockIdx.y * 64;
    const int n0 = blockIdx.x * 64;

    unsigned long long acc[2][4];
#pragma unroll
    for (int p = 0; p < 2; ++p)
#pragma unroll
        for (int q = 0; q < 4; ++q) acc[p][q] = 0ull;

    // staging assignments
    const int a_m = tid >> 2;            // 0..63
    const int a_k = (tid & 3) * 4;       // 0,4,8,12
    const int b_k = tid >> 4;            // 0..15
    const int b_n = (tid & 15) * 4;      // 0..60

    const unsigned as_base = (unsigned)__cvta_generic_to_shared(&As[0][0]);
    const unsigned bs_base = (unsigned)__cvta_generic_to_shared(&Bs[0][0]);
    const unsigned a_rd = as_base + (unsigned)(ty * 16);    // + k*256
    const unsigned b_rd = bs_base + (unsigned)(tx * 32);    // + k*512

    for (int k0 = 0; k0 < K; k0 += 16) {
        float4 av = *reinterpret_cast<const float4*>(
            A + (size_t)(m0 + a_m) * K + (a_k + k0));
        float4 bv = *reinterpret_cast<const float4*>(
            Bw + (size_t)(b_k + k0) * N + (n0 + b_n));
        As[a_k + 0][a_m] = av.x;
        As[a_k + 1][a_m] = av.y;
        As[a_k + 2][a_m] = av.z;
        As[a_k + 3][a_m] = av.w;
        Bs[b_k][b_n + 0] = make_float2(bv.x, bv.x);
        Bs[b_k][b_n + 1] = make_float2(bv.y, bv.y);
        Bs[b_k][b_n + 2] = make_float2(bv.z, bv.z);
        Bs[b_k][b_n + 3] = make_float2(bv.w, bv.w);
        __syncthreads();

#pragma unroll
        for (int k = 0; k < 16; ++k) {
            unsigned long long a01, a23, b0, b1, b2, b3;
            asm volatile("ld.shared.v2.b64 {%0,%1},[%2];"
                         : "=l"(a01), "=l"(a23)
                         : "r"(a_rd + (unsigned)(k * 256)));
            asm volatile("ld.shared.v2.b64 {%0,%1},[%2];"
                         : "=l"(b0), "=l"(b1)
                         : "r"(b_rd + (unsigned)(k * 512)));
            asm volatile("ld.shared.v2.b64 {%0,%1},[%2];"
                         : "=l"(b2), "=l"(b3)
                         : "r"(b_rd + (unsigned)(k * 512 + 16)));
            fma2(acc[0][0], a01, b0);
            fma2(acc[0][1], a01, b1);
            fma2(acc[0][2], a01, b2);
            fma2(acc[0][3], a01, b3);
            fma2(acc[1][0], a23, b0);
            fma2(acc[1][1], a23, b1);
            fma2(acc[1][2], a23, b2);
            fma2(acc[1][3], a23, b3);
        }
        __syncthreads();
    }

#pragma unroll
    for (int q = 0; q < 4; ++q) {
        const int col = n0 + tx * 4 + q;
        const float bb = bias[col];
#pragma unroll
        for (int p = 0; p < 2; ++p) {
            float2 f = *reinterpret_cast<float2*>(&acc[p][q]);
            float v0 = f.x + bb;
            float v1 = f.y + bb;
            if (RELU) {
                v0 = fmaxf(v0, 0.f);
                v1 = fmaxf(v1, 0.f);
            }
            const int row = m0 + ty * 4 + 2 * p;
            C[(size_t)row * N + col] = v0;
            C[(size_t)(row + 1) * N + col] = v1;
        }
    }
}

// ---------------------------------------------------------------------------
extern "C" void kernel_launch(void* const* d_in, const int* in_sizes, int n_in,
                              void* d_out, int out_size) {
    const float* x  = (const float*)d_in[0];
    const float* W1 = (const float*)d_in[1];
    const float* b1 = (const float*)d_in[2];
    const float* W2 = (const float*)d_in[3];
    const float* b2 = (const float*)d_in[4];
    float* out = (float*)d_out;

    float* feat = nullptr;
    float* hbuf = nullptr;
    cudaGetSymbolAddress((void**)&feat, g_feat);
    cudaGetSymbolAddress((void**)&hbuf, g_hbuf);

    // 1) reduction: 512 slabs (B*C), one CTA each
    reduce_kernel<<<512, 256>>>(x);

    // 2) h = relu(feat @ W1 + b1): M=768, N=1536, K=128
    gemm_kernel<true><<<dim3(1536 / 64, 768 / 64), 256>>>(feat, W1, b1, hbuf,
                                                          768, 1536, 128);

    // 3) out = h @ W2 + b2: M=768, N=768, K=1536
    gemm_kernel<false><<<dim3(768 / 64, 768 / 64), 256>>>(hbuf, W2, b2, out,
                                                          768, 768, 1536);
}

// round 2
// speedup vs baseline: 1.5421x; 1.5421x over previous
#include <cuda_runtime.h>
#include <cstdint>
#include <cstddef>

// Problem constants: B=4, C=128, N=64, HID=1536, PROJ=768
// feat: [768, 128], h: [768, 1536], out: [768, 768]

__device__ float g_feat[768 * 128];
__device__ float g_hbuf[768 * 1536];
// partial buffer: GEMM2 split-4 needs 4*768*768 = 2359296 floats
__device__ float g_part[2359296];

// ---------------------------------------------------------------------------
// Kernel 1: streaming reduction. One CTA per (b,c) slab of 64^3 floats (1 MB).
// Warp w owns d in [8w, 8w+8). Lane l = j + 16u (j in [0,16), u in {0,1}).
// Within a slab, lane handles rows r = u + 2i (i = 0..31), float4 column j.
// Hot loop: 32 independent LDG.128 + squares/accumulate. No shuffles/atomics.
// Per slab: one 5-level warp reduce for the d-sum (written straight to g_feat).
// Tail: h partials reduced over j by shuffle then 8-way shared atomics;
// w partials via 16-way shared atomics. Both tiny vs the 1MB stream.
// ---------------------------------------------------------------------------
__global__ void __launch_bounds__(256) reduce_kernel(const float* __restrict__ x) {
    __shared__ float ss_s[64];   // per-h
    __shared__ float sa_s[64];   // per-w
    const int tid = threadIdx.x;
    if (tid < 64) { ss_s[tid] = 0.f; sa_s[tid] = 0.f; }
    __syncthreads();

    const int bc   = blockIdx.x;        // b*128 + c
    const int warp = tid >> 5;
    const int lane = tid & 31;
    const int j    = lane & 15;
    const int u    = lane >> 4;
    const int b    = bc >> 7;
    const int c    = bc & 127;

    const float4* base = reinterpret_cast<const float4*>(x) + (size_t)bc * 65536;

    float hreg[32];
#pragma unroll
    for (int i = 0; i < 32; ++i) hreg[i] = 0.f;
    float w0 = 0.f, w1 = 0.f, w2 = 0.f, w3 = 0.f;

    for (int s = 0; s < 8; ++s) {
        const int d = warp * 8 + s;
        const float4* p = base + d * 1024 + u * 16 + j;   // row (u+2i): +32*i
        float dacc = 0.f;
#pragma unroll
        for (int i = 0; i < 32; ++i) {
            float4 v = p[i * 32];
            float s0 = v.x * v.x, s1 = v.y * v.y, s2 = v.z * v.z, s3 = v.w * v.w;
            w0 += s0; w1 += s1; w2 += s2; w3 += s3;
            float sm = (s0 + s1) + (s2 + s3);
            hreg[i] += sm;
            dacc    += sm;
        }
        // warp-reduce dacc (whole warp covered slab d)
        dacc += __shfl_xor_sync(0xffffffffu, dacc, 16);
        dacc += __shfl_xor_sync(0xffffffffu, dacc, 8);
        dacc += __shfl_xor_sync(0xffffffffu, dacc, 4);
        dacc += __shfl_xor_sync(0xffffffffu, dacc, 2);
        dacc += __shfl_xor_sync(0xffffffffu, dacc, 1);
        if (lane == 0)
            g_feat[(size_t)(b * 192 + d) * 128 + c] = dacc * (1.0f / 4096.0f);
    }

    // h: reduce each hreg[i] over the 16 j-lanes, then 8-way (warp) atomics.
#pragma unroll
    for (int i = 0; i < 32; ++i) {
        float v = hreg[i];
        v += __shfl_xor_sync(0xffffffffu, v, 1);
        v += __shfl_xor_sync(0xffffffffu, v, 2);
        v += __shfl_xor_sync(0xffffffffu, v, 4);
        v += __shfl_xor_sync(0xffffffffu, v, 8);
        if (j == 0) atomicAdd(&ss_s[u + 2 * i], v);
    }

    // w: 16-way (u x warps) shared atomics on 64 distinct addresses.
    atomicAdd(&sa_s[4 * j + 0], w0);
    atomicAdd(&sa_s[4 * j + 1], w1);
    atomicAdd(&sa_s[4 * j + 2], w2);
    atomicAdd(&sa_s[4 * j + 3], w3);

    __syncthreads();

    if (tid < 64) {
        g_feat[(size_t)(b * 192 + 64 + tid) * 128 + c] = ss_s[tid] * (1.0f / 4096.0f);
    } else if (tid < 128) {
        const int t = tid - 64;
        g_feat[(size_t)(b * 192 + 128 + t) * 128 + c] = sa_s[t] * (1.0f / 4096.0f);
    }
}

// ---------------------------------------------------------------------------
// FFMA2 SGEMM: 128x128 tile, BK=16, 256 threads, 8x8 microtile.
// Microtile coords split into two 4-wide groups offset by 64 so all shared
// loads are 16B-per-thread contiguous (conflict-free):
//   m in {4ty..4ty+3} u {64+4ty..64+4ty+3}
//   n in {4tx..4tx+3} u {64+4tx..64+4tx+3}
// Per k-step per thread: 4x LDS.128 (64B) + 8 mov-pack + 32 FFMA2 (128 FLOP)
// -> smem 128B/cyc and FFMA2 256 FLOP/cyc both saturate at 128 cyc/k-step/CTA.
// SPLIT: grid.z chunks of K, writes raw partials at C + z*M*N (no bias).
// ---------------------------------------------------------------------------
__device__ __forceinline__ void fma2(unsigned long long& d,
                                     unsigned long long a,
                                     unsigned long long b) {
    asm("fma.rn.f32x2 %0, %1, %2, %0;" : "+l"(d) : "l"(a), "l"(b));
}
__device__ __forceinline__ unsigned long long pack2(float v) {
    unsigned long long r;
    asm("mov.b64 %0, {%1, %1};" : "=l"(r) : "f"(v));
    return r;
}

template <bool RELU, bool SPLIT>
__global__ void __launch_bounds__(256) gemm_kernel(const float* __restrict__ A,
                                                   const float* __restrict__ Bw,
                                                   const float* __restrict__ bias,
                                                   float* __restrict__ C,
                                                   int M, int N, int K, int Kc) {
    __shared__ float As[16][128];   // [k][m]
    __shared__ float Bs[16][128];   // [k][n]

    const int tid = threadIdx.x;
    const int tx = tid & 15;        // n group
    const int ty = tid >> 4;        // m group
    const int m0 = blockIdx.y * 128;
    const int n0 = blockIdx.x * 128;
    const int kstart = SPLIT ? blockIdx.z * Kc : 0;
    const int kend   = SPLIT ? kstart + Kc : K;

    unsigned long long acc[4][8];
#pragma unroll
    for (int i = 0; i < 4; ++i)
#pragma unroll
        for (int q = 0; q < 8; ++q) acc[i][q] = 0ull;

    // staging assignments
    const int a_m = tid >> 1;           // 0..127
    const int a_k = (tid & 1) * 8;      // 0 or 8
    const int b_k = tid >> 4;           // 0..15
    const int b_n = (tid & 15) * 8;     // 0..120

    const unsigned as_base = (unsigned)__cvta_generic_to_shared(&As[0][0]);
    const unsigned bs_base = (unsigned)__cvta_generic_to_shared(&Bs[0][0]);
    const unsigned a_rd = as_base + (unsigned)(ty * 16);   // +k*512, +256 hi
    const unsigned b_rd = bs_base + (unsigned)(tx * 16);   // +k*512, +256 hi

    const float* Ap = A + (size_t)(m0 + a_m) * K + a_k;
    const float* Bp = Bw + (size_t)b_k * N + (n0 + b_n);

    for (int k0 = kstart; k0 < kend; k0 += 16) {
        float4 av0 = *reinterpret_cast<const float4*>(Ap + k0);
        float4 av1 = *reinterpret_cast<const float4*>(Ap + k0 + 4);
        float4 bv0 = *reinterpret_cast<const float4*>(Bp + (size_t)k0 * N);
        float4 bv1 = *reinterpret_cast<const float4*>(Bp + (size_t)k0 * N + 4);
        As[a_k + 0][a_m] = av0.x;
        As[a_k + 1][a_m] = av0.y;
        As[a_k + 2][a_m] = av0.z;
        As[a_k + 3][a_m] = av0.w;
        As[a_k + 4][a_m] = av1.x;
        As[a_k + 5][a_m] = av1.y;
        As[a_k + 6][a_m] = av1.z;
        As[a_k + 7][a_m] = av1.w;
        *reinterpret_cast<float4*>(&Bs[b_k][b_n])     = bv0;
        *reinterpret_cast<float4*>(&Bs[b_k][b_n + 4]) = bv1;
        __syncthreads();

#pragma unroll
        for (int k = 0; k < 16; ++k) {
            unsigned long long a0, a1, a2, a3;
            float bx0, bx1, bx2, bx3, by0, by1, by2, by3;
            asm volatile("ld.shared.v2.b64 {%0,%1},[%2];"
                         : "=l"(a0), "=l"(a1)
                         : "r"(a_rd + (unsigned)(k * 512)));
            asm volatile("ld.shared.v2.b64 {%0,%1},[%2];"
                         : "=l"(a2), "=l"(a3)
                         : "r"(a_rd + (unsigned)(k * 512 + 256)));
            asm volatile("ld.shared.v4.f32 {%0,%1,%2,%3},[%4];"
                         : "=f"(bx0), "=f"(bx1), "=f"(bx2), "=f"(bx3)
                         : "r"(b_rd + (unsigned)(k * 512)));
            asm volatile("ld.shared.v4.f32 {%0,%1,%2,%3},[%4];"
                         : "=f"(by0), "=f"(by1), "=f"(by2), "=f"(by3)
                         : "r"(b_rd + (unsigned)(k * 512 + 256)));
            unsigned long long bb[8];
            bb[0] = pack2(bx0); bb[1] = pack2(bx1);
            bb[2] = pack2(bx2); bb[3] = pack2(bx3);
            bb[4] = pack2(by0); bb[5] = pack2(by1);
            bb[6] = pack2(by2); bb[7] = pack2(by3);
#pragma unroll
            for (int q = 0; q < 8; ++q) {
                fma2(acc[0][q], a0, bb[q]);
                fma2(acc[1][q], a1, bb[q]);
                fma2(acc[2][q], a2, bb[q]);
                fma2(acc[3][q], a3, bb[q]);
            }
        }
        __syncthreads();
    }

    // epilogue
    float* Cout = SPLIT ? (C + (size_t)blockIdx.z * M * N) : C;
#pragma unroll
    for (int i = 0; i < 4; ++i) {
        const int mrow = m0 + ((i < 2) ? (ty * 4 + 2 * i) : (64 + ty * 4 + 2 * (i - 2)));
#pragma unroll
        for (int q = 0; q < 8; ++q) {
            const int col = n0 + ((q < 4) ? (tx * 4 + q) : (64 + tx * 4 + (q - 4)));
            float2 f = *reinterpret_cast<float2*>(&acc[i][q]);
            float v0 = f.x, v1 = f.y;
            if (!SPLIT) {
                const float bb = bias[col];
                v0 += bb; v1 += bb;
                if (RELU) { v0 = fmaxf(v0, 0.f); v1 = fmaxf(v1, 0.f); }
            }
            Cout[(size_t)mrow * N + col]       = v0;
            Cout[(size_t)(mrow + 1) * N + col] = v1;
        }
    }
}

// ---------------------------------------------------------------------------
// Combine split-K=4 partials + bias. 768*768 floats = 147456 float4.
// ---------------------------------------------------------------------------
__global__ void __launch_bounds__(256) combine_kernel(const float* __restrict__ part,
                                                      const float* __restrict__ bias,
                                                      float* __restrict__ out) {
    const int i = blockIdx.x * 256 + threadIdx.x;     // float4 index
    const float4* p = reinterpret_cast<const float4*>(part);
    float4 a = p[i];
    float4 b = p[i + 147456];
    float4 cc = p[i + 2 * 147456];
    float4 d = p[i + 3 * 147456];
    float4 bb = reinterpret_cast<const float4*>(bias)[i % 192];  // N=768 -> 192 f4/row
    float4 r;
    r.x = ((a.x + b.x) + (cc.x + d.x)) + bb.x;
    r.y = ((a.y + b.y) + (cc.y + d.y)) + bb.y;
    r.z = ((a.z + b.z) + (cc.z + d.z)) + bb.z;
    r.w = ((a.w + b.w) + (cc.w + d.w)) + bb.w;
    reinterpret_cast<float4*>(out)[i] = r;
}

// ---------------------------------------------------------------------------
extern "C" void kernel_launch(void* const* d_in, const int* in_sizes, int n_in,
                              void* d_out, int out_size) {
    const float* x  = (const float*)d_in[0];
    const float* W1 = (const float*)d_in[1];
    const float* b1 = (const float*)d_in[2];
    const float* W2 = (const float*)d_in[3];
    const float* b2 = (const float*)d_in[4];
    float* out = (float*)d_out;

    float* feat = nullptr;
    float* hbuf = nullptr;
    float* part = nullptr;
    cudaGetSymbolAddress((void**)&feat, g_feat);
    cudaGetSymbolAddress((void**)&hbuf, g_hbuf);
    cudaGetSymbolAddress((void**)&part, g_part);

    // 1) reduction: 512 slabs (B*C), one CTA each (single wave, all resident)
    reduce_kernel<<<512, 256>>>(x);

    // 2) h = relu(feat @ W1 + b1): M=768, N=1536, K=128. 12x6 = 72 CTAs.
    gemm_kernel<true, false><<<dim3(1536 / 128, 768 / 128), 256>>>(
        feat, W1, b1, hbuf, 768, 1536, 128, 128);

    // 3) out = h @ W2 + b2: M=768, N=768, K=1536, split-K=4 -> 6x6x4 = 144 CTAs
    gemm_kernel<false, true><<<dim3(768 / 128, 768 / 128, 4), 256>>>(
        hbuf, W2, nullptr, part, 768, 768, 1536, 384);

    // 4) out = sum(partials) + b2
    combine_kernel<<<576, 256>>>(part, b2, out);
}

// round 3
// speedup vs baseline: 1.8229x; 1.1821x over previous
#include <cuda_runtime.h>
#include <cstdint>
#include <cstddef>

// Problem constants: B=4, C=128, N=64, HID=1536, PROJ=768
// feat: [768, 128], h: [768, 1536], out: [768, 768]

__device__ float g_feat[768 * 128];
__device__ float g_hbuf[768 * 1536];
__device__ float g_part[4 * 768 * 768];

// ---------------------------------------------------------------------------
// Kernel 1: streaming reduction. One CTA per (b,c) slab of 64^3 floats (1 MB).
// 4 warps cooperate on one d-slab (16 rows each) so per-thread h-accumulator
// count is 8 (not 32) -> ~55 regs -> occ>=4 -> all 512 CTAs resident (1 wave).
// warp: q = warp&3 (row quarter), half = warp>>2 (d parity).
// lane: j = lane&15 (float4 column), u = lane>>4. Rows h = 16q + u + 2i.
// ---------------------------------------------------------------------------
__global__ void __launch_bounds__(256, 4) reduce_kernel(const float* __restrict__ x) {
    __shared__ float sc_s[64];   // per-d (atomic)
    __shared__ float ss_s[64];   // per-h (atomic)
    __shared__ float sa_s[64];   // per-w (atomic)
    const int tid = threadIdx.x;
    if (tid < 64) { sc_s[tid] = 0.f; ss_s[tid] = 0.f; sa_s[tid] = 0.f; }
    __syncthreads();

    const int bc   = blockIdx.x;        // b*128 + c
    const int warp = tid >> 5;
    const int lane = tid & 31;
    const int q    = warp & 3;
    const int half = warp >> 2;
    const int j    = lane & 15;
    const int u    = lane >> 4;

    const float4* base = reinterpret_cast<const float4*>(x) + (size_t)bc * 65536
                         + (16 * q + u) * 16 + j;

    float hreg[8];
#pragma unroll
    for (int i = 0; i < 8; ++i) hreg[i] = 0.f;
    float w0 = 0.f, w1 = 0.f, w2 = 0.f, w3 = 0.f;

    for (int dd = 0; dd < 32; ++dd) {
        const int d = 2 * dd + half;
        const float4* p = base + d * 1024;
        float dacc = 0.f;
#pragma unroll
        for (int i = 0; i < 8; ++i) {
            float4 v = p[i * 32];
            float s0 = v.x * v.x, s1 = v.y * v.y, s2 = v.z * v.z, s3 = v.w * v.w;
            w0 += s0; w1 += s1; w2 += s2; w3 += s3;
            float sm = (s0 + s1) + (s2 + s3);
            hreg[i] += sm;
            dacc    += sm;
        }
        dacc += __shfl_xor_sync(0xffffffffu, dacc, 16);
        dacc += __shfl_xor_sync(0xffffffffu, dacc, 8);
        dacc += __shfl_xor_sync(0xffffffffu, dacc, 4);
        dacc += __shfl_xor_sync(0xffffffffu, dacc, 2);
        dacc += __shfl_xor_sync(0xffffffffu, dacc, 1);
        if (lane == 0) atomicAdd(&sc_s[d], dacc);
    }

    // h partials: reduce each hreg[i] over the 16 j-lanes; lanes 0 and 16
    // (j==0, u=0/1) then accumulate into shared (2-way across d-halves).
#pragma unroll
    for (int i = 0; i < 8; ++i) {
        float v = hreg[i];
        v += __shfl_xor_sync(0xffffffffu, v, 1);
        v += __shfl_xor_sync(0xffffffffu, v, 2);
        v += __shfl_xor_sync(0xffffffffu, v, 4);
        v += __shfl_xor_sync(0xffffffffu, v, 8);
        if (j == 0) atomicAdd(&ss_s[16 * q + u + 2 * i], v);
    }

    // w partials: 64 distinct slots, <=2-way same-address within a warp.
    atomicAdd(&sa_s[4 * j + 0], w0);
    atomicAdd(&sa_s[4 * j + 1], w1);
    atomicAdd(&sa_s[4 * j + 2], w2);
    atomicAdd(&sa_s[4 * j + 3], w3);

    __syncthreads();

    const int b = bc >> 7;
    const int c = bc & 127;
    if (tid < 192) {
        float v = (tid < 64) ? sc_s[tid]
                : (tid < 128) ? ss_s[tid - 64]
                : sa_s[tid - 128];
        g_feat[(size_t)(b * 192 + tid) * 128 + c] = v * (1.0f / 4096.0f);
    }
}

// ---------------------------------------------------------------------------
// FFMA2 SGEMM: 128x128 tile, BK=16, 256 threads, 8x8 microtile, smem
// double-buffered with register prefetch (1 syncthreads per BK-tile).
// A stored DUPLICATED as float2 (v,v): reads are ty-indexed -> warp broadcast,
// conflict-free. B stored plain: consecutive n floats read as natural f32x2
// pairs (no pack movs). Per k-step per thread: 6 LDS + 32 FFMA2 (128 FLOP).
// Microtile m in {4ty..4ty+3, 64+4ty..+3}; n in {4tx..4tx+3, 64+4tx..+3}.
// SPLIT: grid.z chunks of K; raw partials at C + z*M*N (no bias).
// ---------------------------------------------------------------------------
__device__ __forceinline__ void fma2(unsigned long long& d,
                                     unsigned long long a,
                                     unsigned long long b) {
    asm("fma.rn.f32x2 %0, %1, %2, %0;" : "+l"(d) : "l"(a), "l"(b));
}
__device__ __forceinline__ float2 u2f(unsigned long long v) {
    float2 f;
    asm("mov.b64 {%0,%1}, %2;" : "=f"(f.x), "=f"(f.y) : "l"(v));
    return f;
}

template <bool RELU, bool SPLIT>
__global__ void __launch_bounds__(256) gemm_kernel(const float* __restrict__ A,
                                                   const float* __restrict__ Bw,
                                                   const float* __restrict__ bias,
                                                   float* __restrict__ C,
                                                   int M, int N, int K, int Kc) {
    __shared__ float2 As[2][16][128];   // [stage][k][m], duplicated (v,v)
    __shared__ float  Bs[2][16][128];   // [stage][k][n], plain

    const int tid = threadIdx.x;
    const int tx = tid & 15;
    const int ty = tid >> 4;
    const int m0 = blockIdx.y * 128;
    const int n0 = blockIdx.x * 128;
    const int kstart = SPLIT ? blockIdx.z * Kc : 0;
    const int T = (SPLIT ? Kc : K) >> 4;

    unsigned long long acc[8][4];
#pragma unroll
    for (int i = 0; i < 8; ++i)
#pragma unroll
        for (int p = 0; p < 4; ++p) acc[i][p] = 0ull;

    // staging assignments
    const int a_m = tid >> 1;           // 0..127
    const int a_k = (tid & 1) * 8;      // 0 or 8
    const int b_k = tid >> 4;           // 0..15
    const int b_n = (tid & 15) * 8;     // 0..120

    const float* Ap = A + (size_t)(m0 + a_m) * K + kstart + a_k;
    const float* Bp = Bw + (size_t)(kstart + b_k) * N + n0 + b_n;

    const unsigned as_base = (unsigned)__cvta_generic_to_shared(&As[0][0][0]);
    const unsigned bs_base = (unsigned)__cvta_generic_to_shared(&Bs[0][0][0]);
    const unsigned a_rd = as_base + (unsigned)(ty * 32);   // +k*1024, +512 hi
    const unsigned b_rd = bs_base + (unsigned)(tx * 16);   // +k*512,  +256 hi

    // prologue: prefetch tile 0 and stage into buffer 0
    float4 pa0 = *reinterpret_cast<const float4*>(Ap);
    float4 pa1 = *reinterpret_cast<const float4*>(Ap + 4);
    float4 pb0 = *reinterpret_cast<const float4*>(Bp);
    float4 pb1 = *reinterpret_cast<const float4*>(Bp + 4);
    {
        As[0][a_k + 0][a_m] = make_float2(pa0.x, pa0.x);
        As[0][a_k + 1][a_m] = make_float2(pa0.y, pa0.y);
        As[0][a_k + 2][a_m] = make_float2(pa0.z, pa0.z);
        As[0][a_k + 3][a_m] = make_float2(pa0.w, pa0.w);
        As[0][a_k + 4][a_m] = make_float2(pa1.x, pa1.x);
        As[0][a_k + 5][a_m] = make_float2(pa1.y, pa1.y);
        As[0][a_k + 6][a_m] = make_float2(pa1.z, pa1.z);
        As[0][a_k + 7][a_m] = make_float2(pa1.w, pa1.w);
        *reinterpret_cast<float4*>(&Bs[0][b_k][b_n])     = pb0;
        *reinterpret_cast<float4*>(&Bs[0][b_k][b_n + 4]) = pb1;
    }
    __syncthreads();

    for (int t = 0; ; ) {
        const int st = t & 1;
        const bool more = (t + 1 < T);
        if (more) {
            pa0 = *reinterpret_cast<const float4*>(Ap + (t + 1) * 16);
            pa1 = *reinterpret_cast<const float4*>(Ap + (t + 1) * 16 + 4);
            pb0 = *reinterpret_cast<const float4*>(Bp + (size_t)(t + 1) * 16 * N);
            pb1 = *reinterpret_cast<const float4*>(Bp + (size_t)(t + 1) * 16 * N + 4);
        }

        const unsigned ao = a_rd + (unsigned)(st * 16384);
        const unsigned bo = b_rd + (unsigned)(st * 8192);
#pragma unroll
        for (int k = 0; k < 16; ++k) {
            unsigned long long am[8], bp[4];
            asm volatile("ld.shared.v2.b64 {%0,%1},[%2];"
                         : "=l"(am[0]), "=l"(am[1])
                         : "r"(ao + (unsigned)(k * 1024)));
            asm volatile("ld.shared.v2.b64 {%0,%1},[%2];"
                         : "=l"(am[2]), "=l"(am[3])
                         : "r"(ao + (unsigned)(k * 1024 + 16)));
            asm volatile("ld.shared.v2.b64 {%0,%1},[%2];"
                         : "=l"(am[4]), "=l"(am[5])
                         : "r"(ao + (unsigned)(k * 1024 + 512)));
            asm volatile("ld.shared.v2.b64 {%0,%1},[%2];"
                         : "=l"(am[6]), "=l"(am[7])
                         : "r"(ao + (unsigned)(k * 1024 + 528)));
            asm volatile("ld.shared.v2.b64 {%0,%1},[%2];"
                         : "=l"(bp[0]), "=l"(bp[1])
                         : "r"(bo + (unsigned)(k * 512)));
            asm volatile("ld.shared.v2.b64 {%0,%1},[%2];"
                         : "=l"(bp[2]), "=l"(bp[3])
                         : "r"(bo + (unsigned)(k * 512 + 256)));
#pragma unroll
            for (int i = 0; i < 8; ++i) {
                fma2(acc[i][0], am[i], bp[0]);
                fma2(acc[i][1], am[i], bp[1]);
                fma2(acc[i][2], am[i], bp[2]);
                fma2(acc[i][3], am[i], bp[3]);
            }
        }

        if (!more) break;
        const int ns = (t + 1) & 1;
        As[ns][a_k + 0][a_m] = make_float2(pa0.x, pa0.x);
        As[ns][a_k + 1][a_m] = make_float2(pa0.y, pa0.y);
        As[ns][a_k + 2][a_m] = make_float2(pa0.z, pa0.z);
        As[ns][a_k + 3][a_m] = make_float2(pa0.w, pa0.w);
        As[ns][a_k + 4][a_m] = make_float2(pa1.x, pa1.x);
        As[ns][a_k + 5][a_m] = make_float2(pa1.y, pa1.y);
        As[ns][a_k + 6][a_m] = make_float2(pa1.z, pa1.z);
        As[ns][a_k + 7][a_m] = make_float2(pa1.w, pa1.w);
        *reinterpret_cast<float4*>(&Bs[ns][b_k][b_n])     = pb0;
        *reinterpret_cast<float4*>(&Bs[ns][b_k][b_n + 4]) = pb1;
        __syncthreads();
        ++t;
    }

    // epilogue: acc[i][p] = (C[m][np_lo], C[m][np_hi]) for consecutive n pair
    float* Cout = SPLIT ? (C + (size_t)blockIdx.z * M * N) : C;
    float4 bl = make_float4(0.f, 0.f, 0.f, 0.f);
    float4 bh = bl;
    if (!SPLIT) {
        bl = *reinterpret_cast<const float4*>(&bias[n0 + 4 * tx]);
        bh = *reinterpret_cast<const float4*>(&bias[n0 + 64 + 4 * tx]);
    }
#pragma unroll
    for (int i = 0; i < 8; ++i) {
        const int m = m0 + ((i < 4) ? (4 * ty + i) : (64 + 4 * ty + i - 4));
        float2 f0 = u2f(acc[i][0]);
        float2 f1 = u2f(acc[i][1]);
        float2 f2 = u2f(acc[i][2]);
        float2 f3 = u2f(acc[i][3]);
        float4 lo = make_float4(f0.x, f0.y, f1.x, f1.y);
        float4 hi = make_float4(f2.x, f2.y, f3.x, f3.y);
        if (!SPLIT) {
            lo.x += bl.x; lo.y += bl.y; lo.z += bl.z; lo.w += bl.w;
            hi.x += bh.x; hi.y += bh.y; hi.z += bh.z; hi.w += bh.w;
            if (RELU) {
                lo.x = fmaxf(lo.x, 0.f); lo.y = fmaxf(lo.y, 0.f);
                lo.z = fmaxf(lo.z, 0.f); lo.w = fmaxf(lo.w, 0.f);
                hi.x = fmaxf(hi.x, 0.f); hi.y = fmaxf(hi.y, 0.f);
                hi.z = fmaxf(hi.z, 0.f); hi.w = fmaxf(hi.w, 0.f);
            }
        }
        *reinterpret_cast<float4*>(&Cout[(size_t)m * N + n0 + 4 * tx]) = lo;
        *reinterpret_cast<float4*>(&Cout[(size_t)m * N + n0 + 64 + 4 * tx]) = hi;
    }
}

// ---------------------------------------------------------------------------
// Combine split-K=4 partials + bias. 768*768 floats = 147456 float4.
// ---------------------------------------------------------------------------
__global__ void __launch_bounds__(256) combine_kernel(const float* __restrict__ part,
                                                      const float* __restrict__ bias,
                                                      float* __restrict__ out) {
    const int i = blockIdx.x * 256 + threadIdx.x;
    const float4* p = reinterpret_cast<const float4*>(part);
    float4 a = p[i];
    float4 b = p[i + 147456];
    float4 cc = p[i + 2 * 147456];
    float4 d = p[i + 3 * 147456];
    float4 bb = reinterpret_cast<const float4*>(bias)[i % 192];
    float4 r;
    r.x = ((a.x + b.x) + (cc.x + d.x)) + bb.x;
    r.y = ((a.y + b.y) + (cc.y + d.y)) + bb.y;
    r.z = ((a.z + b.z) + (cc.z + d.z)) + bb.z;
    r.w = ((a.w + b.w) + (cc.w + d.w)) + bb.w;
    reinterpret_cast<float4*>(out)[i] = r;
}

// ---------------------------------------------------------------------------
extern "C" void kernel_launch(void* const* d_in, const int* in_sizes, int n_in,
                              void* d_out, int out_size) {
    const float* x  = (const float*)d_in[0];
    const float* W1 = (const float*)d_in[1];
    const float* b1 = (const float*)d_in[2];
    const float* W2 = (const float*)d_in[3];
    const float* b2 = (const float*)d_in[4];
    float* out = (float*)d_out;

    float* feat = nullptr;
    float* hbuf = nullptr;
    float* part = nullptr;
    cudaGetSymbolAddress((void**)&feat, g_feat);
    cudaGetSymbolAddress((void**)&hbuf, g_hbuf);
    cudaGetSymbolAddress((void**)&part, g_part);

    // 1) reduction: 512 slabs, one CTA each, occ>=4 -> single wave
    reduce_kernel<<<512, 256>>>(x);

    // 2) h = relu(feat @ W1 + b1): M=768, N=1536, K=128 -> 12x6 = 72 CTAs
    gemm_kernel<true, false><<<dim3(12, 6), 256>>>(feat, W1, b1, hbuf,
                                                   768, 1536, 128, 128);

    // 3) partials = h @ W2 (split-K=4): M=768, N=768, K=1536 -> 6x6x4 CTAs
    gemm_kernel<false, true><<<dim3(6, 6, 4), 256>>>(hbuf, W2, nullptr, part,
                                                     768, 768, 1536, 384);

    // 4) out = sum(partials) + b2
    combine_kernel<<<576, 256>>>(part, b2, out);
}